// round 13
// baseline (speedup 1.0000x reference)
#include <cuda_runtime.h>
#include <cuda_fp16.h>

// SSIM_79886391705722 — fused separable-Gaussian SSIM, f32x2, f16x2 staging,
// 256 threads / 6 blocks-SM (48 warps), 32x40 tile, exact-fit phases.
// GB300 sm_103a.  (R12 fix: 16B-align the s_h region.)
// raw/dst: [32,3,512,512] f32. Crop 4 -> 11x11 gaussian (valid) -> SSIM
// (scale-folded C1=1e-4, C2=9e-4) -> per-batch mean [32].

typedef unsigned long long u64;
typedef unsigned int u32;

#define NTHR    256
#define TILE_W  32
#define TILE_H  40
#define IN_H    50     // TILE_H + 10
#define P_RD    43     // u32 pitch (odd)
#define P_H     33     // ulonglong2 pitch (odd)
#define OUT_DIM 494

#define SZ_RD   ((IN_H * P_RD * 4 + 15) & ~15) // 8608, 16B-aligned for s_h
#define SZ_H    (IN_H * P_H * 16)              // 26400
#define SMEM_BYTES (SZ_RD + SZ_H + 64)         // 35072

// Normalized 1D Gaussian (ws=11, sigma=1.5); symmetric
#define G0 0.00102838f
#define G1 0.00759875f
#define G2 0.03600078f
#define G3 0.10936070f
#define G4 0.21300554f
#define G5 0.26601173f

__device__ __forceinline__ u64 pack2(float lo, float hi) {
    u64 r; asm("mov.b64 %0, {%1,%2};" : "=l"(r) : "f"(lo), "f"(hi)); return r;
}
__device__ __forceinline__ void unpack2(u64 v, float& lo, float& hi) {
    asm("mov.b64 {%0,%1}, %2;" : "=f"(lo), "=f"(hi) : "l"(v));
}
__device__ __forceinline__ u64 fma2(u64 a, u64 b, u64 c) {
    u64 r; asm("fma.rn.f32x2 %0, %1, %2, %3;" : "=l"(r) : "l"(a), "l"(b), "l"(c)); return r;
}
// pack (r,d) as f16x2: lo=r, hi=d
__device__ __forceinline__ u32 hpair(float r, float d) {
    u32 p; asm("cvt.rn.f16x2.f32 %0, %1, %2;" : "=r"(p) : "f"(d), "f"(r)); return p;
}

__global__ __launch_bounds__(32) void ssim_zero(float* out) {
    out[threadIdx.x] = 0.0f;
}

__global__ __launch_bounds__(NTHR, 6) void ssim_main(const float* __restrict__ raw,
                                                     const float* __restrict__ dst,
                                                     float* __restrict__ out) {
    extern __shared__ char smem_raw[];
    u32*        s_rd  = reinterpret_cast<u32*>(smem_raw);            // f16x2 (r,d)
    ulonglong2* s_h   = reinterpret_cast<ulonglong2*>(smem_raw + SZ_RD);
    float*      s_red = reinterpret_cast<float*>(smem_raw + SZ_RD + SZ_H);

    const int tid = threadIdx.x;
    const int z   = blockIdx.z;                  // b*3 + c
    const size_t plane = (size_t)z * 512 * 512;
    const float* rp = raw + plane;
    const float* dp = dst + plane;

    const float gv[6] = {G0, G1, G2, G3, G4, G5};
    u64 g2v[6];
    #pragma unroll
    for (int i = 0; i < 6; i++) g2v[i] = pack2(gv[i], gv[i]);
    #define GW2(j) g2v[(j) < 6 ? (j) : 10 - (j)]

    const int oyb0 = blockIdx.y * TILE_H;        // first output row of tile
    const int row0 = oyb0 + 4;
    const int col0 = blockIdx.x * TILE_W + 4;    // ≡ 4 mod 32 -> float4 aligned

    // Rows of the h-plane actually needed by valid outputs (uniform per block).
    int ylim = OUT_DIM - oyb0 + 10;
    if (ylim > IN_H) ylim = IN_H;
    // h-cols needed by valid outputs (last x tile: outputs x<=13 -> strips<24).
    const int xlim = (blockIdx.x == 15) ? 24 : 32;

    // ---- Phase 1: load ylim x 42 halo of (r,d) as f16x2, float4 loads ----
    // 11 groups of 4 pixels per row; group 10 stores only 2 (42-wide halo).
    for (int i = tid; i < ylim * 11; i += NTHR) {
        int y = i / 11;
        int g = i - y * 11;
        int x = g << 2;
        int gr = row0 + y, gc = col0 + x;
        float4 r4 = make_float4(0.f, 0.f, 0.f, 0.f);
        float4 d4 = r4;
        if (gr <= 511 && gc <= 508) {            // gc % 4 == 0: no partial case
            size_t off = (size_t)gr * 512 + gc;
            r4 = __ldg(reinterpret_cast<const float4*>(rp + off));
            d4 = __ldg(reinterpret_cast<const float4*>(dp + off));
        }
        int sb = y * P_RD + x;
        s_rd[sb]     = hpair(r4.x, d4.x);
        s_rd[sb + 1] = hpair(r4.y, d4.y);
        if (g < 10) {
            s_rd[sb + 2] = hpair(r4.z, d4.z);
            s_rd[sb + 3] = hpair(r4.w, d4.w);
        }
    }
    __syncthreads();

    // ---- Phase 2: horizontal 11-tap, strip-4; 8 strips x 64 y-slots ----
    // Warp = 32 consecutive y at one strip -> conflict-free LDS.32 / STS.128.
    for (int s = tid; s < 512; s += NTHR) {
        int y  = (s & 31) | ((s >> 8) << 5);     // [0,64)
        int x0 = ((s >> 5) & 7) << 2;
        if (y < ylim && x0 < xlim) {
            const u32* base = &s_rd[y * P_RD + x0];
            u64 am[4] = {0, 0, 0, 0};
            u64 aq[4] = {0, 0, 0, 0};
            #pragma unroll
            for (int i = 0; i < 14; i++) {
                u32 v = base[i];
                float2 f = __half22float2(*reinterpret_cast<const __half2*>(&v));
                float r = f.x, d = f.y;
                u64 m = pack2(r, d);
                u64 q = pack2(fmaf(r, r, d * d), r * d);
                #pragma unroll
                for (int k = 0; k < 4; k++) {
                    int j = i - k;
                    if (j >= 0 && j < 11) {
                        am[k] = fma2(GW2(j), m, am[k]);
                        aq[k] = fma2(GW2(j), q, aq[k]);
                    }
                }
            }
            int hb = y * P_H + x0;
            #pragma unroll
            for (int k = 0; k < 4; k++) {
                ulonglong2 hp; hp.x = am[k]; hp.y = aq[k];
                s_h[hb + k] = hp;
            }
        }
    }
    __syncthreads();

    // ---- Phase 3: vertical 11-tap, strip-5; 8 warps x 5 = 40 rows exact ----
    float local = 0.0f;
    {
        int x  = tid & 31;
        int y0 = (tid >> 5) * 5;                 // 0..35; max read y = 49
        int ox  = blockIdx.x * TILE_W + x;
        int oyb = oyb0 + y0;
        if (ox < OUT_DIM && oyb < OUT_DIM) {
            u64 am[5], aq[5];
            #pragma unroll
            for (int k = 0; k < 5; k++) { am[k] = 0; aq[k] = 0; }
            const ulonglong2* bh = &s_h[y0 * P_H + x];
            #pragma unroll
            for (int j = 0; j < 15; j++) {
                ulonglong2 hp = bh[j * P_H];
                #pragma unroll
                for (int k = 0; k < 5; k++) {
                    int t = j - k;
                    if (t >= 0 && t < 11) {
                        am[k] = fma2(GW2(t), hp.x, am[k]);
                        aq[k] = fma2(GW2(t), hp.y, aq[k]);
                    }
                }
            }
            const float C1 = 1.0e-4f;    // (0.01)^2  — 255 scale folded out
            const float C2 = 9.0e-4f;    // (0.03)^2
            #pragma unroll
            for (int k = 0; k < 5; k++) {
                if ((oyb + k) < OUT_DIM) {
                    float a, b, srrdd, srd;
                    unpack2(am[k], a, b);
                    unpack2(aq[k], srrdd, srd);
                    float ab  = a * b;
                    float cov = srd - ab;
                    float var = srrdd - a * a - b * b;
                    float num = (2.0f * ab + C1) * (2.0f * cov + C2);
                    float den = (a * a + b * b + C1) * (var + C2);
                    local += __fdividef(num, den);
                }
            }
        }
    }

    #pragma unroll
    for (int o = 16; o > 0; o >>= 1)
        local += __shfl_down_sync(0xffffffff, local, o);
    if ((tid & 31) == 0) s_red[tid >> 5] = local;
    __syncthreads();
    if (tid < 8) {
        local = s_red[tid];
        #pragma unroll
        for (int o = 4; o > 0; o >>= 1)
            local += __shfl_down_sync(0xff, local, o);
        if (tid == 0)
            atomicAdd(&out[z / 3], local * (1.0f / 732108.0f)); // 1/(3*494^2)
    }
}

extern "C" void kernel_launch(void* const* d_in, const int* in_sizes, int n_in,
                              void* d_out, int out_size) {
    const float* raw = (const float*)d_in[0];
    const float* dst = (const float*)d_in[1];
    float* out = (float*)d_out;

    cudaFuncSetAttribute(ssim_main, cudaFuncAttributeMaxDynamicSharedMemorySize,
                         SMEM_BYTES);

    ssim_zero<<<1, 32>>>(out);
    dim3 grid(16, 13, 96);   // 32x40 tiles over 494x494, z = b*3+c
    ssim_main<<<grid, NTHR, SMEM_BYTES>>>(raw, dst, out);
}

// round 14
// speedup vs baseline: 1.1132x; 1.1132x over previous
#include <cuda_runtime.h>
#include <cuda_fp16.h>

// SSIM_79886391705722 — fused separable-Gaussian SSIM, f32x2, f16x2 staging,
// 288 threads / 5 blocks-SM, 32x54 tile, early-exit, PACKED f32x2 epilogue.
// GB300 sm_103a.
// raw/dst: [32,3,512,512] f32. Crop 4 -> 11x11 gaussian (valid) -> SSIM
// (scale-folded C1=1e-4, C2=9e-4) -> per-batch mean [32].

typedef unsigned long long u64;
typedef unsigned int u32;

#define NTHR    288
#define TILE_W  32
#define TILE_H  54
#define IN_H    64     // TILE_H + 10
#define P_RD    43     // u32 pitch (odd)
#define P_H     33     // ulonglong2 pitch (odd)
#define OUT_DIM 494

#define SZ_RD   ((IN_H * P_RD * 4 + 15) & ~15) // 11008, 16B-aligned
#define SZ_H    (IN_H * P_H * 16)              // 33792
#define SMEM_BYTES (SZ_RD + SZ_H + 64)         // 44864

// Normalized 1D Gaussian (ws=11, sigma=1.5); symmetric
#define G0 0.00102838f
#define G1 0.00759875f
#define G2 0.03600078f
#define G3 0.10936070f
#define G4 0.21300554f
#define G5 0.26601173f

__device__ __forceinline__ u64 pack2(float lo, float hi) {
    u64 r; asm("mov.b64 %0, {%1,%2};" : "=l"(r) : "f"(lo), "f"(hi)); return r;
}
__device__ __forceinline__ void unpack2(u64 v, float& lo, float& hi) {
    asm("mov.b64 {%0,%1}, %2;" : "=f"(lo), "=f"(hi) : "l"(v));
}
__device__ __forceinline__ u64 mul2(u64 a, u64 b) {
    u64 r; asm("mul.rn.f32x2 %0, %1, %2;" : "=l"(r) : "l"(a), "l"(b)); return r;
}
__device__ __forceinline__ u64 add2(u64 a, u64 b) {
    u64 r; asm("add.rn.f32x2 %0, %1, %2;" : "=l"(r) : "l"(a), "l"(b)); return r;
}
__device__ __forceinline__ u64 fma2(u64 a, u64 b, u64 c) {
    u64 r; asm("fma.rn.f32x2 %0, %1, %2, %3;" : "=l"(r) : "l"(a), "l"(b), "l"(c)); return r;
}
// pack (r,d) as f16x2: lo=r, hi=d
__device__ __forceinline__ u32 hpair(float r, float d) {
    u32 p; asm("cvt.rn.f16x2.f32 %0, %1, %2;" : "=r"(p) : "f"(d), "f"(r)); return p;
}

__global__ __launch_bounds__(32) void ssim_zero(float* out) {
    out[threadIdx.x] = 0.0f;
}

__global__ __launch_bounds__(NTHR, 5) void ssim_main(const float* __restrict__ raw,
                                                     const float* __restrict__ dst,
                                                     float* __restrict__ out) {
    extern __shared__ char smem_raw[];
    u32*        s_rd  = reinterpret_cast<u32*>(smem_raw);            // f16x2 (r,d)
    ulonglong2* s_h   = reinterpret_cast<ulonglong2*>(smem_raw + SZ_RD);
    float*      s_red = reinterpret_cast<float*>(smem_raw + SZ_RD + SZ_H);

    const int tid = threadIdx.x;
    const int z   = blockIdx.z;                  // b*3 + c
    const size_t plane = (size_t)z * 512 * 512;
    const float* rp = raw + plane;
    const float* dp = dst + plane;

    const float gv[6] = {G0, G1, G2, G3, G4, G5};
    u64 g2v[6];
    #pragma unroll
    for (int i = 0; i < 6; i++) g2v[i] = pack2(gv[i], gv[i]);
    #define GW2(j) g2v[(j) < 6 ? (j) : 10 - (j)]

    const int oyb0 = blockIdx.y * TILE_H;        // first output row of tile
    const int row0 = oyb0 + 4;
    const int col0 = blockIdx.x * TILE_W + 4;    // ≡ 4 mod 32 -> float4 aligned

    // Rows of the h-plane actually needed by valid outputs (uniform per block).
    int ylim = OUT_DIM - oyb0 + 10;
    if (ylim > IN_H) ylim = IN_H;
    // h-cols needed by valid outputs (last x tile: outputs x<=13 -> strips<24).
    const int xlim = (blockIdx.x == 15) ? 24 : 42;

    // ---- Phase 1: load ylim x 42 halo of (r,d) as f16x2, float4 loads ----
    for (int i = tid; i < ylim * 11; i += NTHR) {
        int y = i / 11;
        int g = i - y * 11;
        int x = g << 2;
        int gr = row0 + y, gc = col0 + x;
        float4 r4 = make_float4(0.f, 0.f, 0.f, 0.f);
        float4 d4 = r4;
        if (gr <= 511 && gc <= 508) {            // gc % 4 == 0: no partial case
            size_t off = (size_t)gr * 512 + gc;
            r4 = __ldg(reinterpret_cast<const float4*>(rp + off));
            d4 = __ldg(reinterpret_cast<const float4*>(dp + off));
        }
        int sb = y * P_RD + x;
        s_rd[sb]     = hpair(r4.x, d4.x);
        s_rd[sb + 1] = hpair(r4.y, d4.y);
        if (g < 10) {
            s_rd[sb + 2] = hpair(r4.z, d4.z);
            s_rd[sb + 3] = hpair(r4.w, d4.w);
        }
    }
    __syncthreads();

    // ---- Phase 2: horizontal 11-tap, strip-4; 64 rows x 8 strips = 512 ----
    // Warp sees consecutive y at one strip -> conflict-free LDS.32 / STS.128.
    for (int task = tid; task < 512; task += NTHR) {
        int y  = task & 63;
        int x0 = (task >> 6) << 2;
        if (y < ylim && x0 < xlim) {
            const u32* base = &s_rd[y * P_RD + x0];
            u64 am[4] = {0, 0, 0, 0};
            u64 aq[4] = {0, 0, 0, 0};
            #pragma unroll
            for (int i = 0; i < 14; i++) {
                u32 v = base[i];
                float2 f = __half22float2(*reinterpret_cast<const __half2*>(&v));
                float r = f.x, d = f.y;
                u64 m = pack2(r, d);
                u64 q = pack2(fmaf(r, r, d * d), r * d);
                #pragma unroll
                for (int k = 0; k < 4; k++) {
                    int j = i - k;
                    if (j >= 0 && j < 11) {
                        am[k] = fma2(GW2(j), m, am[k]);
                        aq[k] = fma2(GW2(j), q, aq[k]);
                    }
                }
            }
            int hb = y * P_H + x0;
            #pragma unroll
            for (int k = 0; k < 4; k++) {
                ulonglong2 hp; hp.x = am[k]; hp.y = aq[k];
                s_h[hb + k] = hp;
            }
        }
    }
    __syncthreads();

    // ---- Phase 3: vertical 11-tap, strip-6; 9 warps x 6 = 54 rows exact ----
    float local = 0.0f;
    {
        int x  = tid & 31;
        int y0 = (tid >> 5) * 6;                 // 0..48; max read y = 63
        int ox  = blockIdx.x * TILE_W + x;
        int oyb = oyb0 + y0;
        if (ox < OUT_DIM && oyb < OUT_DIM) {
            u64 am[6], aq[6];
            #pragma unroll
            for (int k = 0; k < 6; k++) { am[k] = 0; aq[k] = 0; }
            const ulonglong2* bh = &s_h[y0 * P_H + x];
            #pragma unroll
            for (int j = 0; j < 16; j++) {
                ulonglong2 hp = bh[j * P_H];
                #pragma unroll
                for (int k = 0; k < 6; k++) {
                    int t = j - k;
                    if (t >= 0 && t < 11) {
                        am[k] = fma2(GW2(t), hp.x, am[k]);
                        aq[k] = fma2(GW2(t), hp.y, aq[k]);
                    }
                }
            }
            // Packed f32x2 SSIM epilogue: 3 output pairs per task.
            const u64 C1_2 = pack2(1.0e-4f, 1.0e-4f);   // (0.01)^2 scale-folded
            const u64 C2_2 = pack2(9.0e-4f, 9.0e-4f);   // (0.03)^2
            const u64 TWO2 = pack2(2.0f, 2.0f);
            const u64 NEG1 = pack2(-1.0f, -1.0f);
            #pragma unroll
            for (int k = 0; k < 6; k += 2) {
                float a0, b0, a1, b1, s0, p0, s1, p1;
                unpack2(am[k],     a0, b0);
                unpack2(am[k + 1], a1, b1);
                unpack2(aq[k],     s0, p0);
                unpack2(aq[k + 1], s1, p1);
                u64 A2 = pack2(a0, a1), B2 = pack2(b0, b1);
                u64 S2 = pack2(s0, s1), P2 = pack2(p0, p1);
                u64 AB   = mul2(A2, B2);
                u64 BBt  = mul2(B2, B2);
                u64 M2   = fma2(A2, A2, BBt);            // a^2 + b^2
                u64 DEN1 = add2(M2, C1_2);               // a^2+b^2+C1
                u64 VARC = fma2(NEG1, M2, add2(S2, C2_2)); // var + C2
                u64 COV  = fma2(NEG1, AB, P2);
                u64 NUM  = mul2(fma2(TWO2, AB, C1_2), fma2(TWO2, COV, C2_2));
                u64 DEN  = mul2(DEN1, VARC);
                float n0, n1, d0f, d1f;
                unpack2(NUM, n0, n1);
                unpack2(DEN, d0f, d1f);
                if ((oyb + k)     < OUT_DIM) local += __fdividef(n0, d0f);
                if ((oyb + k + 1) < OUT_DIM) local += __fdividef(n1, d1f);
            }
        }
    }

    #pragma unroll
    for (int o = 16; o > 0; o >>= 1)
        local += __shfl_down_sync(0xffffffff, local, o);
    if ((tid & 31) == 0) s_red[tid >> 5] = local;
    __syncthreads();
    if (tid < 16) {
        local = (tid < 9) ? s_red[tid] : 0.0f;
        #pragma unroll
        for (int o = 8; o > 0; o >>= 1)
            local += __shfl_down_sync(0xffff, local, o);
        if (tid == 0)
            atomicAdd(&out[z / 3], local * (1.0f / 732108.0f)); // 1/(3*494^2)
    }
}

extern "C" void kernel_launch(void* const* d_in, const int* in_sizes, int n_in,
                              void* d_out, int out_size) {
    const float* raw = (const float*)d_in[0];
    const float* dst = (const float*)d_in[1];
    float* out = (float*)d_out;

    cudaFuncSetAttribute(ssim_main, cudaFuncAttributeMaxDynamicSharedMemorySize,
                         SMEM_BYTES);

    ssim_zero<<<1, 32>>>(out);
    dim3 grid(16, 10, 96);   // 32x54 tiles over 494x494, z = b*3+c
    ssim_main<<<grid, NTHR, SMEM_BYTES>>>(raw, dst, out);
}

// round 16
// speedup vs baseline: 1.2052x; 1.0826x over previous
#include <cuda_runtime.h>
#include <cuda_fp16.h>

// SSIM_79886391705722 — fused separable-Gaussian SSIM, f32x2, f16x2 staging,
// 256 threads / 5 blocks-SM, 32x54 tile, strip-8 h-pass, strip-7 v-pass,
// packed f32x2 epilogue. GB300 sm_103a.
// raw/dst: [32,3,512,512] f32. Crop 4 -> 11x11 gaussian (valid) -> SSIM
// (scale-folded C1=1e-4, C2=9e-4) -> per-batch mean [32].

typedef unsigned long long u64;
typedef unsigned int u32;

#define NTHR    256
#define TILE_W  32
#define TILE_H  54
#define IN_H    64     // TILE_H + 10
#define P_RD    43     // u32 pitch (odd)
#define P_H     33     // ulonglong2 pitch (odd)
#define OUT_DIM 494

// Layout: s_h FIRST, s_rd second — phase-3 strip-7 over-reads (rows 64..65)
// land harmlessly in the (dead-by-then) s_rd region.
#define SZ_H    (IN_H * P_H * 16)              // 33792, 16B-aligned
#define SZ_RD   (IN_H * P_RD * 4)              // 11008
#define RED_OFF (SZ_H + SZ_RD)                 // 44800
#define SMEM_BYTES (RED_OFF + 32)              // 44832

// Normalized 1D Gaussian (ws=11, sigma=1.5); symmetric
#define G0 0.00102838f
#define G1 0.00759875f
#define G2 0.03600078f
#define G3 0.10936070f
#define G4 0.21300554f
#define G5 0.26601173f

__device__ __forceinline__ u64 pack2(float lo, float hi) {
    u64 r; asm("mov.b64 %0, {%1,%2};" : "=l"(r) : "f"(lo), "f"(hi)); return r;
}
__device__ __forceinline__ void unpack2(u64 v, float& lo, float& hi) {
    asm("mov.b64 {%0,%1}, %2;" : "=f"(lo), "=f"(hi) : "l"(v));
}
__device__ __forceinline__ u64 mul2(u64 a, u64 b) {
    u64 r; asm("mul.rn.f32x2 %0, %1, %2;" : "=l"(r) : "l"(a), "l"(b)); return r;
}
__device__ __forceinline__ u64 add2(u64 a, u64 b) {
    u64 r; asm("add.rn.f32x2 %0, %1, %2;" : "=l"(r) : "l"(a), "l"(b)); return r;
}
__device__ __forceinline__ u64 fma2(u64 a, u64 b, u64 c) {
    u64 r; asm("fma.rn.f32x2 %0, %1, %2, %3;" : "=l"(r) : "l"(a), "l"(b), "l"(c)); return r;
}
// pack (r,d) as f16x2: lo=r, hi=d
__device__ __forceinline__ u32 hpair(float r, float d) {
    u32 p; asm("cvt.rn.f16x2.f32 %0, %1, %2;" : "=r"(p) : "f"(d), "f"(r)); return p;
}

__global__ __launch_bounds__(32) void ssim_zero(float* out) {
    out[threadIdx.x] = 0.0f;
}

__global__ __launch_bounds__(NTHR, 5) void ssim_main(const float* __restrict__ raw,
                                                     const float* __restrict__ dst,
                                                     float* __restrict__ out) {
    extern __shared__ char smem_raw[];
    ulonglong2* s_h   = reinterpret_cast<ulonglong2*>(smem_raw);      // {m, q}
    u32*        s_rd  = reinterpret_cast<u32*>(smem_raw + SZ_H);      // f16x2 (r,d)
    float*      s_red = reinterpret_cast<float*>(smem_raw + RED_OFF);

    const int tid = threadIdx.x;
    const int z   = blockIdx.z;                  // b*3 + c
    const size_t plane = (size_t)z * 512 * 512;
    const float* rp = raw + plane;
    const float* dp = dst + plane;

    const float gv[6] = {G0, G1, G2, G3, G4, G5};
    u64 g2v[6];
    #pragma unroll
    for (int i = 0; i < 6; i++) g2v[i] = pack2(gv[i], gv[i]);
    #define GW2(j) g2v[(j) < 6 ? (j) : 10 - (j)]

    const int oyb0 = blockIdx.y * TILE_H;        // first output row of tile
    const int row0 = oyb0 + 4;
    const int col0 = blockIdx.x * TILE_W + 4;    // ≡ 4 mod 32 -> float4 aligned

    // Rows of the h-plane actually needed by valid outputs (uniform per block).
    int ylim = OUT_DIM - oyb0 + 10;
    if (ylim > IN_H) ylim = IN_H;
    // h-cols needed (last x tile: outputs x<=13 -> cols<24 -> strips {0,8,16}).
    const int xlim = (blockIdx.x == 15) ? 24 : 32;

    // ---- Phase 1: load ylim x 42 halo of (r,d) as f16x2, float4 loads ----
    for (int i = tid; i < ylim * 11; i += NTHR) {
        int y = i / 11;
        int g = i - y * 11;
        int x = g << 2;
        int gr = row0 + y, gc = col0 + x;
        float4 r4 = make_float4(0.f, 0.f, 0.f, 0.f);
        float4 d4 = r4;
        if (gr <= 511 && gc <= 508) {            // gc % 4 == 0: no partial case
            size_t off = (size_t)gr * 512 + gc;
            r4 = __ldg(reinterpret_cast<const float4*>(rp + off));
            d4 = __ldg(reinterpret_cast<const float4*>(dp + off));
        }
        int sb = y * P_RD + x;
        s_rd[sb]     = hpair(r4.x, d4.x);
        s_rd[sb + 1] = hpair(r4.y, d4.y);
        if (g < 10) {
            s_rd[sb + 2] = hpair(r4.z, d4.z);
            s_rd[sb + 3] = hpair(r4.w, d4.w);
        }
    }
    __syncthreads();

    // ---- Phase 2: horizontal 11-tap, strip-8; 64 rows x 4 strips = 256 ----
    // Warp = 32 consecutive y at one strip -> conflict-free LDS.32 / STS.128.
    {
        int y  = tid & 63;
        int x0 = (tid >> 6) << 3;                // 0, 8, 16, 24
        if (y < ylim && x0 < xlim) {
            const u32* base = &s_rd[y * P_RD + x0];
            u64 am[8], aq[8];
            #pragma unroll
            for (int k = 0; k < 8; k++) { am[k] = 0; aq[k] = 0; }
            #pragma unroll
            for (int i = 0; i < 18; i++) {
                u32 v = base[i];
                float2 f = __half22float2(*reinterpret_cast<const __half2*>(&v));
                float r = f.x, d = f.y;
                u64 m = pack2(r, d);
                u64 q = pack2(fmaf(r, r, d * d), r * d);
                #pragma unroll
                for (int k = 0; k < 8; k++) {
                    int j = i - k;
                    if (j >= 0 && j < 11) {
                        am[k] = fma2(GW2(j), m, am[k]);
                        aq[k] = fma2(GW2(j), q, aq[k]);
                    }
                }
            }
            int hb = y * P_H + x0;
            #pragma unroll
            for (int k = 0; k < 8; k++) {
                ulonglong2 hp; hp.x = am[k]; hp.y = aq[k];
                s_h[hb + k] = hp;
            }
        }
    }
    __syncthreads();

    // ---- Phase 3: vertical 11-tap, strip-7; 8 warps x 7 = 56 >= 54 rows ----
    // Warp 7 (y0=49) reads rows up to 65: rows 64..65 land in the dead s_rd
    // region (garbage); tap predicate t<11 routes them only to k>=5 ->
    // y0+k >= TILE_H -> discarded by the guard below.
    float local = 0.0f;
    {
        int x  = tid & 31;
        int y0 = (tid >> 5) * 7;                 // 0,7,...,49
        int ox  = blockIdx.x * TILE_W + x;
        int oyb = oyb0 + y0;
        if (ox < OUT_DIM && oyb < OUT_DIM) {
            u64 am[7], aq[7];
            #pragma unroll
            for (int k = 0; k < 7; k++) { am[k] = 0; aq[k] = 0; }
            const ulonglong2* bh = &s_h[y0 * P_H + x];
            #pragma unroll
            for (int j = 0; j < 17; j++) {
                ulonglong2 hp = bh[j * P_H];
                #pragma unroll
                for (int k = 0; k < 7; k++) {
                    int t = j - k;
                    if (t >= 0 && t < 11) {
                        am[k] = fma2(GW2(t), hp.x, am[k]);
                        aq[k] = fma2(GW2(t), hp.y, aq[k]);
                    }
                }
            }
            // Packed f32x2 SSIM epilogue: 3 pairs + 1 scalar.
            const u64 C1_2 = pack2(1.0e-4f, 1.0e-4f);   // (0.01)^2 scale-folded
            const u64 C2_2 = pack2(9.0e-4f, 9.0e-4f);   // (0.03)^2
            const u64 TWO2 = pack2(2.0f, 2.0f);
            const u64 NEG1 = pack2(-1.0f, -1.0f);
            #pragma unroll
            for (int k = 0; k < 6; k += 2) {
                float a0, b0, a1, b1, s0, p0, s1, p1;
                unpack2(am[k],     a0, b0);
                unpack2(am[k + 1], a1, b1);
                unpack2(aq[k],     s0, p0);
                unpack2(aq[k + 1], s1, p1);
                u64 A2 = pack2(a0, a1), B2 = pack2(b0, b1);
                u64 S2 = pack2(s0, s1), P2 = pack2(p0, p1);
                u64 AB   = mul2(A2, B2);
                u64 BBt  = mul2(B2, B2);
                u64 M2   = fma2(A2, A2, BBt);              // a^2 + b^2
                u64 DEN1 = add2(M2, C1_2);
                u64 VARC = fma2(NEG1, M2, add2(S2, C2_2)); // var + C2
                u64 COV  = fma2(NEG1, AB, P2);
                u64 NUM  = mul2(fma2(TWO2, AB, C1_2), fma2(TWO2, COV, C2_2));
                u64 DEN  = mul2(DEN1, VARC);
                float n0, n1, d0f, d1f;
                unpack2(NUM, n0, n1);
                unpack2(DEN, d0f, d1f);
                if ((y0 + k)     < TILE_H && (oyb + k)     < OUT_DIM)
                    local += __fdividef(n0, d0f);
                if ((y0 + k + 1) < TILE_H && (oyb + k + 1) < OUT_DIM)
                    local += __fdividef(n1, d1f);
            }
            if ((y0 + 6) < TILE_H && (oyb + 6) < OUT_DIM) {
                float a, b, s, p;
                unpack2(am[6], a, b);
                unpack2(aq[6], s, p);
                float ab  = a * b;
                float cov = p - ab;
                float m2  = a * a + b * b;
                float num = (2.0f * ab + 1.0e-4f) * (2.0f * cov + 9.0e-4f);
                float den = (m2 + 1.0e-4f) * ((s - m2) + 9.0e-4f);
                local += __fdividef(num, den);
            }
        }
    }

    #pragma unroll
    for (int o = 16; o > 0; o >>= 1)
        local += __shfl_down_sync(0xffffffff, local, o);
    if ((tid & 31) == 0) s_red[tid >> 5] = local;
    __syncthreads();
    if (tid < 8) {
        local = s_red[tid];
        #pragma unroll
        for (int o = 4; o > 0; o >>= 1)
            local += __shfl_down_sync(0xff, local, o);
        if (tid == 0)
            atomicAdd(&out[z / 3], local * (1.0f / 732108.0f)); // 1/(3*494^2)
    }
}

extern "C" void kernel_launch(void* const* d_in, const int* in_sizes, int n_in,
                              void* d_out, int out_size) {
    const float* raw = (const float*)d_in[0];
    const float* dst = (const float*)d_in[1];
    float* out = (float*)d_out;

    cudaFuncSetAttribute(ssim_main, cudaFuncAttributeMaxDynamicSharedMemorySize,
                         SMEM_BYTES);

    ssim_zero<<<1, 32>>>(out);
    dim3 grid(16, 10, 96);   // 32x54 tiles over 494x494, z = b*3+c
    ssim_main<<<grid, NTHR, SMEM_BYTES>>>(raw, dst, out);
}